// round 11
// baseline (speedup 1.0000x reference)
#include <cuda_runtime.h>
#include <math.h>

#define NNODES 100000
#define NGRAPH 256
#define NCLASS 10
#define NEG 0.2f
#define CAP 96
#define FULLM 0xffffffffu

// ---------------- scratch (static device globals; no allocation) ----------------
__device__ __align__(16) float g_H[NNODES * 64];
__device__ __align__(16) float g_A[NNODES * 64];
__device__ __align__(16) float g_B[NNODES * 64];
__device__ float g_s[NNODES];
__device__ float g_d[NNODES];
__device__ int   g_cnt[NNODES];            // zero at call entry (restored by k_poolfc)
__device__ int   g_slot[NNODES * CAP];     // bucketed adjacency (src per dst)

__device__ __forceinline__ float lrelu(float x) { return x > 0.f ? x : NEG * x; }

// ---------------- GEMM body (float4 smem weight reads) ----------------
template <int FIN, int FOUT, int TPN>
__device__ __forceinline__ void gemmsd_body(int bx, int tid,
                                            const float* __restrict__ X,
                                            const float* __restrict__ W,
                                            const float* __restrict__ asrc,
                                            const float* __restrict__ adst,
                                            float* __restrict__ H,
                                            float* smem) {
    constexpr int FO = FOUT / TPN;
    float* sw = smem;
    float* sa = smem + FIN * FOUT;
    float* sdv = sa + FOUT;
    for (int i = tid; i < FIN * FOUT; i += 256) sw[i] = W[i];
    if (tid < FOUT) { sa[tid] = asrc[tid]; sdv[tid] = adst[tid]; }
    __syncthreads();
    int t = bx * 256 + tid;
    int n = t / TPN, part = t % TPN;
    bool valid = n < NNODES;
    int nc = valid ? n : NNODES - 1;
    const float4* xr = reinterpret_cast<const float4*>(X + (long)nc * FIN);
    float acc[FO];
#pragma unroll
    for (int q = 0; q < FO; q++) acc[q] = 0.f;
#pragma unroll
    for (int k4 = 0; k4 < FIN / 4; k4++) {
        float4 xv = xr[k4];
        float xs[4] = {xv.x, xv.y, xv.z, xv.w};
#pragma unroll
        for (int r = 0; r < 4; r++) {
            const float4* wr = reinterpret_cast<const float4*>(
                sw + (k4 * 4 + r) * FOUT + part * FO);
#pragma unroll
            for (int q4 = 0; q4 < FO / 4; q4++) {
                float4 wv = wr[q4];
                acc[q4 * 4 + 0] = fmaf(xs[r], wv.x, acc[q4 * 4 + 0]);
                acc[q4 * 4 + 1] = fmaf(xs[r], wv.y, acc[q4 * 4 + 1]);
                acc[q4 * 4 + 2] = fmaf(xs[r], wv.z, acc[q4 * 4 + 2]);
                acc[q4 * 4 + 3] = fmaf(xs[r], wv.w, acc[q4 * 4 + 3]);
            }
        }
    }
    if (valid) {
        float4* hr = reinterpret_cast<float4*>(H + (long)n * FOUT + part * FO);
#pragma unroll
        for (int q4 = 0; q4 < FO / 4; q4++)
            hr[q4] = make_float4(acc[q4 * 4], acc[q4 * 4 + 1], acc[q4 * 4 + 2], acc[q4 * 4 + 3]);
    }
    float s = 0.f, d = 0.f;
#pragma unroll
    for (int q = 0; q < FO; q++) {
        s = fmaf(acc[q], sa[part * FO + q], s);
        d = fmaf(acc[q], sdv[part * FO + q], d);
    }
    if (TPN == 2) {
        s += __shfl_xor_sync(FULLM, s, 1);
        d += __shfl_xor_sync(FULLM, d, 1);
    }
    if (valid && part == 0) { g_s[n] = s; g_d[n] = d; }
}

template <int FIN, int FOUT, int TPN>
__global__ void __launch_bounds__(256) k_gemmsd(const float* __restrict__ X,
                                                const float* __restrict__ W,
                                                const float* __restrict__ asrc,
                                                const float* __restrict__ adst,
                                                float* __restrict__ H) {
    __shared__ float smem[FIN * FOUT + 2 * FOUT];
    gemmsd_body<FIN, FOUT, TPN>(blockIdx.x, threadIdx.x, X, W, asrc, adst, H, smem);
}

// fused: blocks [0, GB1) do gemm1; blocks [GB1, ...) scatter edges into buckets
#define GB1 ((NNODES + 255) / 256)
__global__ void __launch_bounds__(256) k_sg1(const int* __restrict__ src,
                                             const int* __restrict__ dst, int E,
                                             const float* __restrict__ X,
                                             const float* __restrict__ W,
                                             const float* __restrict__ asrc,
                                             const float* __restrict__ adst,
                                             float* __restrict__ H) {
    __shared__ float smem[128 * 16 + 32];
    if (blockIdx.x < GB1) {
        gemmsd_body<128, 16, 1>(blockIdx.x, threadIdx.x, X, W, asrc, adst, H, smem);
    } else {
        int e = (blockIdx.x - GB1) * 256 + threadIdx.x;
        if (e < E) {
            int d = dst[e];
            int pos = atomicAdd(&g_cnt[d], 1);
            if (pos < CAP) g_slot[d * CAP + pos] = src[e];
        }
    }
}

// ---------------- GAT aggregation: L = FOUT/8 lanes per node, 2 float4/lane -------
// R9 structure (no smem, no inner-loop shuffles) with halved lane-group size:
// scalar (slot, g_s, exp) redundancy drops 2x; useful float4 gathers unchanged.
template <int FOUT>
__global__ void __launch_bounds__(256) k_agg(const float* __restrict__ H,
                                             const float* __restrict__ b,
                                             float* __restrict__ OUT) {
    constexpr int L = FOUT / 8;            // lanes per node: 2 / 4 / 8
    constexpr int NPB = 256 / L;           // nodes per block
    int grp = threadIdx.x / L;
    int lane = threadIdx.x % L;
    int wlane = threadIdx.x & 31;
    unsigned mask = (((1u << L) - 1u) << (wlane & ~(L - 1)));
    int n = blockIdx.x * NPB + grp;
    if (n >= NNODES) return;

    float s_n = g_s[n];
    float d_n = g_d[n];
    int deg = min(g_cnt[n], CAP);
    const int* slot = g_slot + (long)n * CAP;

    // phase 1: segment max of s over neighbors (warms slot row + g_s into L1)
    float smax = s_n;
    for (int j = lane; j < deg; j += L)
        smax = fmaxf(smax, g_s[slot[j]]);
#pragma unroll
    for (int o = L / 2; o > 0; o >>= 1)
        smax = fmaxf(smax, __shfl_xor_sync(mask, smax, o, L));
    float m = lrelu(smax + d_n);

    // phase 2: weighted aggregation; lane owns float4 chunks 2*lane and 2*lane+1
    float den = 0.f;
    float4 a0 = make_float4(0.f, 0.f, 0.f, 0.f);
    float4 a1 = make_float4(0.f, 0.f, 0.f, 0.f);
#pragma unroll 4
    for (int j = 0; j < deg; j++) {
        int s = slot[j];                                   // L1 hit
        float w = __expf(lrelu(g_s[s] + d_n) - m);         // L1 hit
        den += w;
        const float4* hr = reinterpret_cast<const float4*>(H + (long)s * FOUT);
        float4 h0 = hr[2 * lane];
        float4 h1 = hr[2 * lane + 1];
        a0.x = fmaf(w, h0.x, a0.x);
        a0.y = fmaf(w, h0.y, a0.y);
        a0.z = fmaf(w, h0.z, a0.z);
        a0.w = fmaf(w, h0.w, a0.w);
        a1.x = fmaf(w, h1.x, a1.x);
        a1.y = fmaf(w, h1.y, a1.y);
        a1.z = fmaf(w, h1.z, a1.z);
        a1.w = fmaf(w, h1.w, a1.w);
    }

    float wself = __expf(lrelu(s_n + d_n) - m);
    den += wself;
    float inv = 1.f / (den + 1e-16f);
    const float4* hnr = reinterpret_cast<const float4*>(H + (long)n * FOUT);
    const float4* bbr = reinterpret_cast<const float4*>(b);
    float4 hn0 = hnr[2 * lane], hn1 = hnr[2 * lane + 1];
    float4 bb0 = bbr[2 * lane], bb1 = bbr[2 * lane + 1];
    float4 o0, o1;
    o0.x = fmaxf(fmaf(wself, hn0.x, a0.x) * inv + bb0.x, 0.f);
    o0.y = fmaxf(fmaf(wself, hn0.y, a0.y) * inv + bb0.y, 0.f);
    o0.z = fmaxf(fmaf(wself, hn0.z, a0.z) * inv + bb0.z, 0.f);
    o0.w = fmaxf(fmaf(wself, hn0.w, a0.w) * inv + bb0.w, 0.f);
    o1.x = fmaxf(fmaf(wself, hn1.x, a1.x) * inv + bb1.x, 0.f);
    o1.y = fmaxf(fmaf(wself, hn1.y, a1.y) * inv + bb1.y, 0.f);
    o1.z = fmaxf(fmaf(wself, hn1.z, a1.z) * inv + bb1.z, 0.f);
    o1.w = fmaxf(fmaf(wself, hn1.w, a1.w) * inv + bb1.w, 0.f);
    float4* outr = reinterpret_cast<float4*>(OUT + (long)n * FOUT);
    outr[2 * lane] = o0;
    outr[2 * lane + 1] = o1;
}

// ---------------- fused pool + FC + log_softmax (+ cnt re-zero in extra blocks) ----
__global__ void __launch_bounds__(256) k_poolfc(const float* __restrict__ X,
                                                const int* __restrict__ batch,
                                                const float* __restrict__ fcw,
                                                const float* __restrict__ fcb,
                                                float* __restrict__ out) {
    if (blockIdx.x >= NGRAPH) {
        int n = (blockIdx.x - NGRAPH) * 256 + threadIdx.x;
        if (n < NNODES) g_cnt[n] = 0;
        return;
    }
    int g = blockIdx.x;
    int t = threadIdx.x;
    __shared__ int lohi[2];
    if (t < 2) {
        int target = g + t;
        int lo = 0, hi = NNODES;
        while (lo < hi) {
            int mid = (lo + hi) >> 1;
            if (batch[mid] < target) lo = mid + 1; else hi = mid;
        }
        lohi[t] = lo;
    }
    __syncthreads();
    int f = t & 63, grp = t >> 6;
    float v = 0.f;   // inputs post-relu (>=0), segments non-empty
    for (int n = lohi[0] + grp; n < lohi[1]; n += 4)
        v = fmaxf(v, X[(long)n * 64 + f]);
    __shared__ float sm[256];
    __shared__ float p[64];
    sm[t] = v;
    __syncthreads();
    if (grp == 0)
        p[f] = fmaxf(fmaxf(sm[f], sm[f + 64]), fmaxf(sm[f + 128], sm[f + 192]));
    __syncthreads();
    __shared__ float lg[NCLASS];
    __shared__ float red[2];
    if (t < NCLASS) {
        float acc = fcb[t];
#pragma unroll
        for (int k = 0; k < 64; k++) acc = fmaf(p[k], fcw[k * NCLASS + t], acc);
        lg[t] = acc;
    }
    __syncthreads();
    if (t == 0) {
        float mx = lg[0];
#pragma unroll
        for (int i = 1; i < NCLASS; i++) mx = fmaxf(mx, lg[i]);
        float se = 0.f;
#pragma unroll
        for (int i = 0; i < NCLASS; i++) se += __expf(lg[i] - mx);
        red[0] = mx;
        red[1] = logf(se);
    }
    __syncthreads();
    if (t < NCLASS) out[g * NCLASS + t] = lg[t] - red[0] - red[1];
}

// ---------------- host ----------------

extern "C" void kernel_launch(void* const* d_in, const int* in_sizes, int n_in,
                              void* d_out, int out_size) {
    const float* x     = (const float*)d_in[0];
    const int*   ei    = (const int*)d_in[1];
    const int*   batch = (const int*)d_in[2];
    const float* W1 = (const float*)d_in[3];
    const float* a1s = (const float*)d_in[4];
    const float* a1d = (const float*)d_in[5];
    const float* b1 = (const float*)d_in[6];
    const float* W2 = (const float*)d_in[7];
    const float* a2s = (const float*)d_in[8];
    const float* a2d = (const float*)d_in[9];
    const float* b2 = (const float*)d_in[10];
    const float* W3 = (const float*)d_in[11];
    const float* a3s = (const float*)d_in[12];
    const float* a3d = (const float*)d_in[13];
    const float* b3 = (const float*)d_in[14];
    const float* fcw = (const float*)d_in[15];
    const float* fcb = (const float*)d_in[16];
    float* out = (float*)d_out;

    int E = in_sizes[1] / 2;
    const int* srcp = ei;
    const int* dstp = ei + E;

    float *H, *A, *B;
    cudaGetSymbolAddress((void**)&H, g_H);
    cudaGetSymbolAddress((void**)&A, g_A);
    cudaGetSymbolAddress((void**)&B, g_B);

    const int NT = 256;
    // 1: fused bucket-scatter + layer-1 GEMM (cnt is zero at entry)
    k_sg1<<<GB1 + (E + NT - 1) / NT, NT>>>(srcp, dstp, E, x, W1, a1s, a1d, H);
    // 2: layer-1 aggregation (2 lanes/node)
    k_agg<16><<<(NNODES + 127) / 128, NT>>>(H, b1, A);
    // 3: layer-2 GEMM
    k_gemmsd<16, 32, 1><<<(NNODES + NT - 1) / NT, NT>>>(A, W2, a2s, a2d, H);
    // 4: layer-2 aggregation (profiled slot; 4 lanes/node)
    k_agg<32><<<(NNODES + 63) / 64, NT>>>(H, b2, B);
    // 5: layer-3 GEMM
    k_gemmsd<32, 64, 2><<<(NNODES * 2 + NT - 1) / NT, NT>>>(B, W3, a3s, a3d, H);
    // 6: layer-3 aggregation (8 lanes/node)
    k_agg<64><<<(NNODES + 31) / 32, NT>>>(H, b3, A);
    // 7: pool + fc + log_softmax (+ cnt re-zero)
    k_poolfc<<<NGRAPH + (NNODES + NT - 1) / NT, NT>>>(A, batch, fcw, fcb, out);
}

// round 13
// speedup vs baseline: 1.0395x; 1.0395x over previous
#include <cuda_runtime.h>
#include <math.h>

#define NNODES 100000
#define NGRAPH 256
#define NCLASS 10
#define NEG 0.2f
#define CAP 96
#define FULLM 0xffffffffu

// ---------------- scratch (static device globals; no allocation) ----------------
__device__ __align__(16) float g_H[NNODES * 64];   // H1, later final features
__device__ __align__(16) float g_A[NNODES * 64];   // H2
__device__ __align__(16) float g_B[NNODES * 64];   // H3
__device__ float g_s[NNODES];
__device__ float g_d[NNODES];
__device__ float g_s2[NNODES];
__device__ float g_d2[NNODES];
__device__ int   g_cnt[NNODES];            // zero at call entry (restored by k_poolfc)
__device__ int   g_slot[NNODES * CAP];     // bucketed adjacency (src per dst)

__device__ __forceinline__ float lrelu(float x) { return x > 0.f ? x : NEG * x; }

// ---------------- GEMM body (layer 1 only; float4 smem weight reads) --------------
__device__ __forceinline__ void gemm1_body(int bx, int tid,
                                           const float* __restrict__ X,
                                           const float* __restrict__ W,
                                           const float* __restrict__ asrc,
                                           const float* __restrict__ adst,
                                           float* __restrict__ H,
                                           float* smem) {
    constexpr int FIN = 128, FOUT = 16;
    float* sw = smem;
    float* sa = smem + FIN * FOUT;
    float* sdv = sa + FOUT;
    for (int i = tid; i < FIN * FOUT; i += 256) sw[i] = W[i];
    if (tid < FOUT) { sa[tid] = asrc[tid]; sdv[tid] = adst[tid]; }
    __syncthreads();
    int n = bx * 256 + tid;
    bool valid = n < NNODES;
    int nc = valid ? n : NNODES - 1;
    const float4* xr = reinterpret_cast<const float4*>(X + (long)nc * FIN);
    float acc[FOUT];
#pragma unroll
    for (int q = 0; q < FOUT; q++) acc[q] = 0.f;
#pragma unroll
    for (int k4 = 0; k4 < FIN / 4; k4++) {
        float4 xv = xr[k4];
        float xs[4] = {xv.x, xv.y, xv.z, xv.w};
#pragma unroll
        for (int r = 0; r < 4; r++) {
            const float4* wr = reinterpret_cast<const float4*>(sw + (k4 * 4 + r) * FOUT);
#pragma unroll
            for (int q4 = 0; q4 < FOUT / 4; q4++) {
                float4 wv = wr[q4];
                acc[q4 * 4 + 0] = fmaf(xs[r], wv.x, acc[q4 * 4 + 0]);
                acc[q4 * 4 + 1] = fmaf(xs[r], wv.y, acc[q4 * 4 + 1]);
                acc[q4 * 4 + 2] = fmaf(xs[r], wv.z, acc[q4 * 4 + 2]);
                acc[q4 * 4 + 3] = fmaf(xs[r], wv.w, acc[q4 * 4 + 3]);
            }
        }
    }
    if (valid) {
        float4* hr = reinterpret_cast<float4*>(H + (long)n * FOUT);
#pragma unroll
        for (int q4 = 0; q4 < FOUT / 4; q4++)
            hr[q4] = make_float4(acc[q4 * 4], acc[q4 * 4 + 1], acc[q4 * 4 + 2], acc[q4 * 4 + 3]);
        float s = 0.f, d = 0.f;
#pragma unroll
        for (int q = 0; q < FOUT; q++) {
            s = fmaf(acc[q], sa[q], s);
            d = fmaf(acc[q], sdv[q], d);
        }
        g_s[n] = s;
        g_d[n] = d;
    }
}

// fused: blocks [0, GB1) do gemm1; blocks [GB1, ...) scatter edges into buckets
#define GB1 ((NNODES + 255) / 256)
__global__ void __launch_bounds__(256) k_sg1(const int* __restrict__ src,
                                             const int* __restrict__ dst, int E,
                                             const float* __restrict__ X,
                                             const float* __restrict__ W,
                                             const float* __restrict__ asrc,
                                             const float* __restrict__ adst,
                                             float* __restrict__ H) {
    __shared__ float smem[128 * 16 + 32];
    if (blockIdx.x < GB1) {
        gemm1_body(blockIdx.x, threadIdx.x, X, W, asrc, adst, H, smem);
    } else {
        int e = (blockIdx.x - GB1) * 256 + threadIdx.x;
        if (e < E) {
            int d = dst[e];
            int pos = atomicAdd(&g_cnt[d], 1);
            if (pos < CAP) g_slot[d * CAP + pos] = src[e];
        }
    }
}

// ---------------- fused GAT aggregation + next-layer GEMM -------------------------
// Agg (R9 structure: L=FIN/4 lanes/node, shuffle-free loop, den accumulated FULLY
// in every lane — no reduction!) produces the layer output row in the lane group;
// staged to smem, multiplied by next W in smem. Intermediate features never touch
// global memory.
template <int FIN, int FOUT>
__global__ void __launch_bounds__(256) k_agg_gemm(const float* __restrict__ H,
                                                  const float* __restrict__ bin,
                                                  const float* __restrict__ W,
                                                  const float* __restrict__ asrc,
                                                  const float* __restrict__ adst,
                                                  float* __restrict__ Hout,
                                                  const float* __restrict__ sin_,
                                                  const float* __restrict__ din_,
                                                  float* __restrict__ sout_,
                                                  float* __restrict__ dout_) {
    constexpr int L = FIN / 4;            // lanes per node
    constexpr int NPB = 256 / L;          // nodes per block
    constexpr int FO = FOUT / L;          // next-layer outputs per lane
    __shared__ float sw[FIN * FOUT];
    __shared__ float sa[FOUT], sdv[FOUT];
    __shared__ float sout[NPB * FIN];
    for (int i = threadIdx.x; i < FIN * FOUT; i += 256) sw[i] = W[i];
    if (threadIdx.x < FOUT) {
        sa[threadIdx.x] = asrc[threadIdx.x];
        sdv[threadIdx.x] = adst[threadIdx.x];
    }
    __syncthreads();

    int grp = threadIdx.x / L;
    int lane = threadIdx.x % L;
    int wlane = threadIdx.x & 31;
    unsigned mask = (((1u << L) - 1u) << (wlane & ~(L - 1)));
    int n = blockIdx.x * NPB + grp;
    if (n >= NNODES) return;

    float s_n = sin_[n];
    float d_n = din_[n];
    int deg = min(g_cnt[n], CAP);
    const int* slot = g_slot + (long)n * CAP;

    // phase 1: segment max of s over neighbors
    float smax = s_n;
    for (int j = lane; j < deg; j += L)
        smax = fmaxf(smax, sin_[slot[j]]);
#pragma unroll
    for (int o = L / 2; o > 0; o >>= 1)
        smax = fmaxf(smax, __shfl_xor_sync(mask, smax, o, L));
    float m = lrelu(smax + d_n);

    // phase 2: weighted aggregation; every lane runs the full loop, so den is
    // the COMPLETE sum per lane — no cross-lane reduction.
    float den = 0.f;
    float4 acc = make_float4(0.f, 0.f, 0.f, 0.f);
#pragma unroll 4
    for (int j = 0; j < deg; j++) {
        int s = slot[j];
        float w = __expf(lrelu(sin_[s] + d_n) - m);
        den += w;
        float4 h = reinterpret_cast<const float4*>(H + (long)s * FIN)[lane];
        acc.x = fmaf(w, h.x, acc.x);
        acc.y = fmaf(w, h.y, acc.y);
        acc.z = fmaf(w, h.z, acc.z);
        acc.w = fmaf(w, h.w, acc.w);
    }

    float wself = __expf(lrelu(s_n + d_n) - m);
    den += wself;
    float inv = 1.f / (den + 1e-16f);
    float4 hn = reinterpret_cast<const float4*>(H + (long)n * FIN)[lane];
    float4 bb = reinterpret_cast<const float4*>(bin)[lane];
    float4 o4;
    o4.x = fmaxf(fmaf(wself, hn.x, acc.x) * inv + bb.x, 0.f);
    o4.y = fmaxf(fmaf(wself, hn.y, acc.y) * inv + bb.y, 0.f);
    o4.z = fmaxf(fmaf(wself, hn.z, acc.z) * inv + bb.z, 0.f);
    o4.w = fmaxf(fmaf(wself, hn.w, acc.w) * inv + bb.w, 0.f);
    reinterpret_cast<float4*>(sout + grp * FIN)[lane] = o4;
    __syncwarp(mask);

    // next-layer GEMM from smem: lane owns outputs [lane*FO, lane*FO+FO)
    float ac[FO];
#pragma unroll
    for (int q = 0; q < FO; q++) ac[q] = 0.f;
    const float* srow = sout + grp * FIN;
#pragma unroll
    for (int k = 0; k < FIN; k++) {
        float v = srow[k];
        const float4* wr = reinterpret_cast<const float4*>(sw + k * FOUT + lane * FO);
#pragma unroll
        for (int q4 = 0; q4 < FO / 4; q4++) {
            float4 wv = wr[q4];
            ac[q4 * 4 + 0] = fmaf(v, wv.x, ac[q4 * 4 + 0]);
            ac[q4 * 4 + 1] = fmaf(v, wv.y, ac[q4 * 4 + 1]);
            ac[q4 * 4 + 2] = fmaf(v, wv.z, ac[q4 * 4 + 2]);
            ac[q4 * 4 + 3] = fmaf(v, wv.w, ac[q4 * 4 + 3]);
        }
    }
    // s2/d2 ARE lane-partial (each lane covers FO of FOUT outputs) -> reduce.
    float s2 = 0.f, d2 = 0.f;
#pragma unroll
    for (int q = 0; q < FO; q++) {
        s2 = fmaf(ac[q], sa[lane * FO + q], s2);
        d2 = fmaf(ac[q], sdv[lane * FO + q], d2);
    }
#pragma unroll
    for (int o = L / 2; o > 0; o >>= 1) {
        s2 += __shfl_xor_sync(mask, s2, o, L);
        d2 += __shfl_xor_sync(mask, d2, o, L);
    }
    if (lane == 0) { sout_[n] = s2; dout_[n] = d2; }
    float4* hr = reinterpret_cast<float4*>(Hout + (long)n * FOUT + lane * FO);
#pragma unroll
    for (int q4 = 0; q4 < FO / 4; q4++)
        hr[q4] = make_float4(ac[q4 * 4], ac[q4 * 4 + 1], ac[q4 * 4 + 2], ac[q4 * 4 + 3]);
}

// ---------------- final GAT aggregation (R9 exact; L = FOUT/4, full-lane den) -----
template <int FOUT>
__global__ void __launch_bounds__(256) k_agg(const float* __restrict__ H,
                                             const float* __restrict__ b,
                                             float* __restrict__ OUT) {
    constexpr int L = FOUT / 4;
    constexpr int NPB = 256 / L;
    int grp = threadIdx.x / L;
    int lane = threadIdx.x % L;
    int wlane = threadIdx.x & 31;
    unsigned mask = (L == 32) ? FULLM
                              : (((1u << L) - 1u) << (wlane & ~(L - 1)));
    int n = blockIdx.x * NPB + grp;
    if (n >= NNODES) return;

    float s_n = g_s[n];
    float d_n = g_d[n];
    int deg = min(g_cnt[n], CAP);
    const int* slot = g_slot + (long)n * CAP;

    float smax = s_n;
    for (int j = lane; j < deg; j += L)
        smax = fmaxf(smax, g_s[slot[j]]);
#pragma unroll
    for (int o = L / 2; o > 0; o >>= 1)
        smax = fmaxf(smax, __shfl_xor_sync(mask, smax, o, L));
    float m = lrelu(smax + d_n);

    // full loop per lane: den is complete per lane, NO reduction
    float den = 0.f;
    float4 acc = make_float4(0.f, 0.f, 0.f, 0.f);
#pragma unroll 4
    for (int j = 0; j < deg; j++) {
        int s = slot[j];
        float w = __expf(lrelu(g_s[s] + d_n) - m);
        den += w;
        float4 h = reinterpret_cast<const float4*>(H + (long)s * FOUT)[lane];
        acc.x = fmaf(w, h.x, acc.x);
        acc.y = fmaf(w, h.y, acc.y);
        acc.z = fmaf(w, h.z, acc.z);
        acc.w = fmaf(w, h.w, acc.w);
    }

    float wself = __expf(lrelu(s_n + d_n) - m);
    den += wself;
    float inv = 1.f / (den + 1e-16f);
    float4 hn = reinterpret_cast<const float4*>(H + (long)n * FOUT)[lane];
    float4 bb = reinterpret_cast<const float4*>(b)[lane];
    float4 o4;
    o4.x = fmaxf(fmaf(wself, hn.x, acc.x) * inv + bb.x, 0.f);
    o4.y = fmaxf(fmaf(wself, hn.y, acc.y) * inv + bb.y, 0.f);
    o4.z = fmaxf(fmaf(wself, hn.z, acc.z) * inv + bb.z, 0.f);
    o4.w = fmaxf(fmaf(wself, hn.w, acc.w) * inv + bb.w, 0.f);
    reinterpret_cast<float4*>(OUT + (long)n * FOUT)[lane] = o4;
}

// ---------------- fused pool + FC + log_softmax (+ cnt re-zero in extra blocks) ----
__global__ void __launch_bounds__(256) k_poolfc(const float* __restrict__ X,
                                                const int* __restrict__ batch,
                                                const float* __restrict__ fcw,
                                                const float* __restrict__ fcb,
                                                float* __restrict__ out) {
    if (blockIdx.x >= NGRAPH) {
        int n = (blockIdx.x - NGRAPH) * 256 + threadIdx.x;
        if (n < NNODES) g_cnt[n] = 0;
        return;
    }
    int g = blockIdx.x;
    int t = threadIdx.x;
    __shared__ int lohi[2];
    if (t < 2) {
        int target = g + t;
        int lo = 0, hi = NNODES;
        while (lo < hi) {
            int mid = (lo + hi) >> 1;
            if (batch[mid] < target) lo = mid + 1; else hi = mid;
        }
        lohi[t] = lo;
    }
    __syncthreads();
    int f = t & 63, grp = t >> 6;
    float v = 0.f;   // inputs post-relu (>=0), segments non-empty
    for (int n = lohi[0] + grp; n < lohi[1]; n += 4)
        v = fmaxf(v, X[(long)n * 64 + f]);
    __shared__ float sm[256];
    __shared__ float p[64];
    sm[t] = v;
    __syncthreads();
    if (grp == 0)
        p[f] = fmaxf(fmaxf(sm[f], sm[f + 64]), fmaxf(sm[f + 128], sm[f + 192]));
    __syncthreads();
    __shared__ float lg[NCLASS];
    __shared__ float red[2];
    if (t < NCLASS) {
        float acc = fcb[t];
#pragma unroll
        for (int k = 0; k < 64; k++) acc = fmaf(p[k], fcw[k * NCLASS + t], acc);
        lg[t] = acc;
    }
    __syncthreads();
    if (t == 0) {
        float mx = lg[0];
#pragma unroll
        for (int i = 1; i < NCLASS; i++) mx = fmaxf(mx, lg[i]);
        float se = 0.f;
#pragma unroll
        for (int i = 0; i < NCLASS; i++) se += __expf(lg[i] - mx);
        red[0] = mx;
        red[1] = logf(se);
    }
    __syncthreads();
    if (t < NCLASS) out[g * NCLASS + t] = lg[t] - red[0] - red[1];
}

// ---------------- host ----------------

extern "C" void kernel_launch(void* const* d_in, const int* in_sizes, int n_in,
                              void* d_out, int out_size) {
    const float* x     = (const float*)d_in[0];
    const int*   ei    = (const int*)d_in[1];
    const int*   batch = (const int*)d_in[2];
    const float* W1 = (const float*)d_in[3];
    const float* a1s = (const float*)d_in[4];
    const float* a1d = (const float*)d_in[5];
    const float* b1 = (const float*)d_in[6];
    const float* W2 = (const float*)d_in[7];
    const float* a2s = (const float*)d_in[8];
    const float* a2d = (const float*)d_in[9];
    const float* b2 = (const float*)d_in[10];
    const float* W3 = (const float*)d_in[11];
    const float* a3s = (const float*)d_in[12];
    const float* a3d = (const float*)d_in[13];
    const float* b3 = (const float*)d_in[14];
    const float* fcw = (const float*)d_in[15];
    const float* fcb = (const float*)d_in[16];
    float* out = (float*)d_out;

    int E = in_sizes[1] / 2;
    const int* srcp = ei;
    const int* dstp = ei + E;

    float *H, *A, *B, *S, *D, *S2, *D2;
    cudaGetSymbolAddress((void**)&H, g_H);
    cudaGetSymbolAddress((void**)&A, g_A);
    cudaGetSymbolAddress((void**)&B, g_B);
    cudaGetSymbolAddress((void**)&S, g_s);
    cudaGetSymbolAddress((void**)&D, g_d);
    cudaGetSymbolAddress((void**)&S2, g_s2);
    cudaGetSymbolAddress((void**)&D2, g_d2);

    const int NT = 256;
    // 1: fused bucket-scatter + layer-1 GEMM (cnt is zero at entry)
    k_sg1<<<GB1 + (E + NT - 1) / NT, NT>>>(srcp, dstp, E, x, W1, a1s, a1d, H);
    // 2: agg1 (4 lanes/node) + gemm2 fused; H1->H2, s/d -> s2/d2
    k_agg_gemm<16, 32><<<(NNODES + 63) / 64, NT>>>(H, b1, W2, a2s, a2d,
                                                   A, S, D, S2, D2);
    // 3: agg2 (8 lanes/node) + gemm3 fused; H2->H3, s2/d2 -> s/d
    k_agg_gemm<32, 64><<<(NNODES + 31) / 32, NT>>>(A, b2, W3, a3s, a3d,
                                                   B, S2, D2, S, D);
    // 4: final aggregation (16 lanes/node; profiled slot)
    k_agg<64><<<(NNODES + 15) / 16, NT>>>(B, b3, H);
    // 5: pool + fc + log_softmax (+ cnt re-zero)
    k_poolfc<<<NGRAPH + (NNODES + NT - 1) / NT, NT>>>(H, batch, fcw, fcb, out);
}